// round 8
// baseline (speedup 1.0000x reference)
#include <cuda_runtime.h>
#include <stdint.h>
#include <math.h>

#define SEQ_L        200
#define ROWS_PER_BLK 100
#define BLKS_PER_B   2
#define NT           256
#define EPS2         (1e-8f * 1e-8f)

// Partial-triple layout: per row 26 triples (m=0..12 -> chunk0, m=13..25 -> chunk1),
// row stride 79 floats (79 mod 32 = 15, odd => conflict-free scalar LDS/STS).
#define ROW_STRIDE   79
#define SPART_FLOATS (ROWS_PER_BLK * ROW_STRIDE)   // 7900 floats = 31.6 KB

#define MAX_B 8192
__device__ float4 g_part[MAX_B * BLKS_PER_B];

// Half-select dot: half=0 -> full 4-elem dot, half=1 -> x,y only, half=2 -> z,w only.
__device__ __forceinline__ float dsel(float4 v, float4 a, int half) {
    const float xy = fmaf(v.x, a.x, v.y * a.y);
    const float zw = fmaf(v.z, a.z, v.w * a.w);
    return (half == 1) ? xy : ((half == 2) ? zw : xy + zw);
}

// Block = (b, half-of-L). Phase 1: warp-per-row staging computes per-f4 partial
// triples (s, d, wd) during the gather and stores 12B/f4 (raw v never re-read).
// Phase 2: one thread per (row, chunk) sums 13 triples, takes exp, accumulates.
__global__ __launch_bounds__(NT, 5)
void binclf_main(const int*   __restrict__ word_idxs,   // [B, 200]
                 const float* __restrict__ emb_table,   // [100000, 100]
                 const float* __restrict__ weights,     // [100]
                 const float* __restrict__ attend_u)    // [100] chunk-major
{
    __shared__ float spart[SPART_FLOATS];
    __shared__ int   sidx[ROWS_PER_BLK];
    __shared__ float sred[16];

    const int blk  = blockIdx.x;
    const int b    = blk >> 1;
    const int l0   = (blk & 1) * ROWS_PER_BLK;
    const int t    = threadIdx.x;
    const int lane = t & 31;
    const int w    = t >> 5;

    // Lane roles for staging: lanes 0..24 -> f4 slot = lane; lane 25 -> second
    // half of boundary slot 12 (stored at m=25). half: 1 = x,y only (lane 12),
    // 2 = z,w only (lane 25), 0 = full.
    const bool act  = (lane < 26);
    const int  slot = (lane == 25) ? 12 : lane;
    const int  half = (lane == 12) ? 1 : ((lane == 25) ? 2 : 0);

    // u / w for this lane's slot live in registers for the whole kernel.
    float4 u4 = make_float4(0.f, 0.f, 0.f, 0.f);
    float4 w4 = make_float4(0.f, 0.f, 0.f, 0.f);
    if (act) {
        u4 = ((const float4*)attend_u)[slot];
        w4 = ((const float4*)weights)[slot];
    }

    // Stage word indices.
    const int* idxp = word_idxs + (size_t)b * SEQ_L + l0;
    if (t < ROWS_PER_BLK) sidx[t] = __ldg(idxp + t);
    __syncthreads();

    // ---- Phase 1: gather + partial triples. Warp w stages rows w, w+8, ... ----
    #pragma unroll
    for (int kb = 0; kb < 13; kb += 4) {
        float4 v[4];
        int    rr[4];
        #pragma unroll
        for (int q = 0; q < 4; q++) {
            const int r = w + 8 * (kb + q);
            rr[q] = r;
            if (r < ROWS_PER_BLK && act) {
                const int idx = sidx[r];
                v[q] = __ldg((const float4*)(emb_table + (size_t)idx * 100) + slot);
            }
        }
        #pragma unroll
        for (int q = 0; q < 4; q++) {
            if (rr[q] < ROWS_PER_BLK && act) {
                const float4 vv = v[q];
                const float s  = dsel(vv, vv, half);
                const float d  = dsel(vv, u4, half);
                const float wd = dsel(vv, w4, half);
                float* p = spart + rr[q] * ROW_STRIDE + lane * 3;
                p[0] = s; p[1] = d; p[2] = wd;
            }
        }
    }
    __syncthreads();

    // ---- Phase 2: warps 0-3 chunk 0, warps 4-7 chunk 1; lane = row offset ----
    const int c = w >> 2;

    // 1/max(||u_c||, eps) from register-resident u4 (per-warp butterfly).
    {
        const bool in_c = c ? (lane >= 13 && lane <= 25) : (lane <= 12);
        float uu = in_c ? dsel(u4, u4, half) : 0.f;
        #pragma unroll
        for (int o = 16; o > 0; o >>= 1)
            uu += __shfl_xor_sync(0xffffffffu, uu, o);
        float uinv = rsqrtf(fmaxf(uu, EPS2));

        float p = 0.f, A = 0.f;
        if (lane < 25) {
            const int row = (w & 3) * 25 + lane;
            const float* pr = spart + row * ROW_STRIDE + 39 * c;  // 13c triples in
            float s = 0.f, d = 0.f, wd = 0.f;
            #pragma unroll
            for (int j = 0; j < 13; j++) {
                s  += pr[3 * j + 0];
                d  += pr[3 * j + 1];
                wd += pr[3 * j + 2];
            }
            const float a = __expf(d * rsqrtf(fmaxf(s, EPS2)) * uinv);
            p = a * wd;
            A = a;
        }

        #pragma unroll
        for (int o = 16; o > 0; o >>= 1) {
            p += __shfl_xor_sync(0xffffffffu, p, o);
            A += __shfl_xor_sync(0xffffffffu, A, o);
        }
        if (lane == 0) { sred[w * 2] = p; sred[w * 2 + 1] = A; }
    }
    __syncthreads();

    if (t == 0) {
        float p0 = 0.f, A0 = 0.f, p1 = 0.f, A1 = 0.f;
        #pragma unroll
        for (int k = 0; k < 4; k++) {
            p0 += sred[2 * k];         A0 += sred[2 * k + 1];
            p1 += sred[8 + 2 * k];     A1 += sred[8 + 2 * k + 1];
        }
        g_part[blk] = make_float4(p0, A0, p1, A1);
    }
}

__global__ void binclf_fin(float* __restrict__ out, int B)
{
    const int b = blockIdx.x * blockDim.x + threadIdx.x;
    if (b >= B) return;
    const float4 x = g_part[2 * b];
    const float4 y = g_part[2 * b + 1];
    out[b] = (x.x + y.x) / (x.y + y.y) + (x.z + y.z) / (x.w + y.w);
}

extern "C" void kernel_launch(void* const* d_in, const int* in_sizes, int n_in,
                              void* d_out, int out_size)
{
    const int*   word_idxs = (const int*)  d_in[0];  // [B, 200] int32
    const float* emb_table = (const float*)d_in[1];  // [100000, 100] f32
    const float* weights   = (const float*)d_in[2];  // [100, 1] f32
    const float* attend_u  = (const float*)d_in[3];  // [2, 50] f32
    float*       out       = (float*)d_out;          // [B] f32

    const int B = in_sizes[0] / SEQ_L;

    binclf_main<<<B * BLKS_PER_B, NT>>>(word_idxs, emb_table, weights, attend_u);
    binclf_fin<<<(B + 255) / 256, 256>>>(out, B);
}

// round 10
// speedup vs baseline: 2.3392x; 2.3392x over previous
#include <cuda_runtime.h>
#include <stdint.h>
#include <math.h>

#define SEQ_L     200
#define EPS2      (1e-8f * 1e-8f)
#define VOCAB_MAX 100352

// Per-vocab precomputed table: (a0, a0*wd0, a1, a1*wd1)
__device__ float4 g_vtab[VOCAB_MAX];

// Half-select dot: half=0 -> full 4-elem dot, half=1 -> x,y only, half=2 -> z,w only.
__device__ __forceinline__ float dsel(float4 v, float4 a, int half) {
    const float xy = fmaf(v.x, a.x, v.y * a.y);
    const float zw = fmaf(v.z, a.z, v.w * a.w);
    return (half == 1) ? xy : ((half == 2) ? zw : xy + zw);
}

__device__ __forceinline__ float wredsum(float x) {
    #pragma unroll
    for (int o = 16; o > 0; o >>= 1)
        x += __shfl_xor_sync(0xffffffffu, x, o);
    return x;
}

// ---- Kernel 1: per-vocab-row precompute. Warp-per-row, 4 rows per warp. ----
// Lanes 0..24 hold float4 slot = lane; lane 25 re-covers slot 12's z,w (chunk
// boundary at float 50). chunk0 = lanes 0..12 (lane12: x,y), chunk1 = 13..25.
__global__ __launch_bounds__(256)
void binclf_vtab(const float* __restrict__ emb_table,   // [vocab, 100]
                 const float* __restrict__ weights,     // [100]
                 const float* __restrict__ attend_u,    // [100] chunk-major
                 int vocab)
{
    const int t    = threadIdx.x;
    const int lane = t & 31;
    const int w    = t >> 5;

    const bool act  = (lane < 26);
    const int  slot = (lane == 25) ? 12 : lane;
    const int  half = (lane == 12) ? 1 : ((lane == 25) ? 2 : 0);
    const bool c0   = (lane <= 12);
    const bool c1   = (lane >= 13 && lane <= 25);

    float4 u4 = make_float4(0.f, 0.f, 0.f, 0.f);
    float4 w4 = make_float4(0.f, 0.f, 0.f, 0.f);
    if (act) {
        u4 = ((const float4*)attend_u)[slot];
        w4 = ((const float4*)weights)[slot];
    }

    const float uq    = dsel(u4, u4, half);
    const float uinv0 = rsqrtf(fmaxf(wredsum(c0 ? uq : 0.f), EPS2));
    const float uinv1 = rsqrtf(fmaxf(wredsum(c1 ? uq : 0.f), EPS2));

    const int row0 = (blockIdx.x * 8 + w) * 4;

    float4 v[4];
    #pragma unroll
    for (int q = 0; q < 4; q++) {
        v[q] = make_float4(0.f, 0.f, 0.f, 0.f);
        const int r = row0 + q;
        if (r < vocab && act)
            v[q] = __ldg((const float4*)(emb_table + (size_t)r * 100) + slot);
    }

    #pragma unroll
    for (int q = 0; q < 4; q++) {
        const int r = row0 + q;              // warp-uniform
        if (r >= vocab) break;
        const float s  = dsel(v[q], v[q], half);
        const float d  = dsel(v[q], u4,  half);
        const float wd = dsel(v[q], w4,  half);
        const float s0  = wredsum(c0 ? s  : 0.f);
        const float s1  = wredsum(c1 ? s  : 0.f);
        const float d0  = wredsum(c0 ? d  : 0.f);
        const float d1  = wredsum(c1 ? d  : 0.f);
        const float wd0 = wredsum(c0 ? wd : 0.f);
        const float wd1 = wredsum(c1 ? wd : 0.f);
        if (lane == 0) {
            const float a0 = __expf(d0 * rsqrtf(fmaxf(s0, EPS2)) * uinv0);
            const float a1 = __expf(d1 * rsqrtf(fmaxf(s1, EPS2)) * uinv1);
            g_vtab[r] = make_float4(a0, a0 * wd0, a1, a1 * wd1);
        }
    }
}

// ---- Kernel 2: one warp per batch row. 200 words -> 7 strided per lane. ----
__global__ __launch_bounds__(256)
void binclf_accum(const int* __restrict__ word_idxs,    // [B, 200]
                  float*     __restrict__ out,          // [B]
                  int B)
{
    const int t    = threadIdx.x;
    const int lane = t & 31;
    const int w    = t >> 5;
    const int b    = blockIdx.x * 8 + w;
    if (b >= B) return;                     // warp-uniform

    const int* idxp = word_idxs + (size_t)b * SEQ_L;

    int idx[7];
    #pragma unroll
    for (int k = 0; k < 7; k++) {
        const int l = lane + 32 * k;
        idx[k] = (l < SEQ_L) ? __ldg(idxp + l) : -1;
    }

    float A0 = 0.f, P0 = 0.f, A1 = 0.f, P1 = 0.f;
    #pragma unroll
    for (int k = 0; k < 7; k++) {
        if (idx[k] >= 0) {
            const float4 v = __ldg(&g_vtab[idx[k]]);
            A0 += v.x; P0 += v.y; A1 += v.z; P1 += v.w;
        }
    }

    A0 = wredsum(A0); P0 = wredsum(P0);
    A1 = wredsum(A1); P1 = wredsum(P1);

    if (lane == 0)
        out[b] = P0 / A0 + P1 / A1;
}

extern "C" void kernel_launch(void* const* d_in, const int* in_sizes, int n_in,
                              void* d_out, int out_size)
{
    const int*   word_idxs = (const int*)  d_in[0];  // [B, 200] int32
    const float* emb_table = (const float*)d_in[1];  // [vocab, 100] f32
    const float* weights   = (const float*)d_in[2];  // [100, 1] f32
    const float* attend_u  = (const float*)d_in[3];  // [2, 50] f32
    float*       out       = (float*)d_out;          // [B] f32

    const int B     = in_sizes[0] / SEQ_L;
    const int vocab = in_sizes[1] / 100;

    // 32 rows per block (8 warps x 4 rows)
    binclf_vtab<<<(vocab + 31) / 32, 256>>>(emb_table, weights, attend_u, vocab);
    binclf_accum<<<(B + 7) / 8, 256>>>(word_idxs, out, B);
}

// round 11
// speedup vs baseline: 2.7473x; 1.1745x over previous
#include <cuda_runtime.h>
#include <stdint.h>
#include <math.h>

#define SEQ_L     200
#define EPS2      (1e-8f * 1e-8f)
#define VOCAB_MAX 100352

// Per-vocab precomputed table: (a0, a0*wd0, a1, a1*wd1)
__device__ float4 g_vtab[VOCAB_MAX];

// Half-select dot: half=0 -> full 4-elem dot, half=1 -> x,y only, half=2 -> z,w only.
__device__ __forceinline__ float dsel(float4 v, float4 a, int half) {
    const float xy = fmaf(v.x, a.x, v.y * a.y);
    const float zw = fmaf(v.z, a.z, v.w * a.w);
    return (half == 1) ? xy : ((half == 2) ? zw : xy + zw);
}

// 4-step butterfly confined to each 16-lane half (inactive lanes hold 0).
__device__ __forceinline__ float hredsum(float x) {
    #pragma unroll
    for (int o = 8; o > 0; o >>= 1)
        x += __shfl_xor_sync(0xffffffffu, x, o);
    return x;
}

__device__ __forceinline__ float wredsum(float x) {
    #pragma unroll
    for (int o = 16; o > 0; o >>= 1)
        x += __shfl_xor_sync(0xffffffffu, x, o);
    return x;
}

// ---- Kernel 1: per-vocab-row precompute, 4 rows per warp. ----
// Chunk 0 (floats 0..49)  -> lanes 0..12  (f4 slots 0..12, lane 12 = x,y only)
// Chunk 1 (floats 50..99) -> lanes 16..28 (f4 slots 12..24, lane 16 = z,w only)
// Both chunks reduce simultaneously with 4-step half-warp butterflies; lanes 0
// and 16 each finish their chunk and write an independent 8-byte half of g_vtab.
__global__ __launch_bounds__(256)
void binclf_vtab(const float* __restrict__ emb_table,   // [vocab, 100]
                 const float* __restrict__ weights,     // [100]
                 const float* __restrict__ attend_u,    // [100] chunk-major
                 int vocab)
{
    const int t    = threadIdx.x;
    const int lane = t & 31;
    const int w    = t >> 5;

    const bool lo   = (lane <= 12);
    const bool hi   = (lane >= 16 && lane <= 28);
    const bool act  = lo || hi;
    const int  slot = lo ? lane : (lane - 4);            // hi: 16..28 -> 12..24
    const int  half = (lane == 12) ? 1 : ((lane == 16) ? 2 : 0);

    float4 u4 = make_float4(0.f, 0.f, 0.f, 0.f);
    float4 w4 = make_float4(0.f, 0.f, 0.f, 0.f);
    if (act) {
        u4 = ((const float4*)attend_u)[slot];
        w4 = ((const float4*)weights)[slot];
    }

    // 1/max(||u_c||, eps): one half-warp butterfly serves both chunks.
    const float uinv = rsqrtf(fmaxf(hredsum(act ? dsel(u4, u4, half) : 0.f), EPS2));

    const int row0 = (blockIdx.x * 8 + w) * 4;

    float4 v[4];
    #pragma unroll
    for (int q = 0; q < 4; q++) {
        v[q] = make_float4(0.f, 0.f, 0.f, 0.f);
        const int r = row0 + q;
        if (r < vocab && act)
            v[q] = __ldg((const float4*)(emb_table + (size_t)r * 100) + slot);
    }

    #pragma unroll
    for (int q = 0; q < 4; q++) {
        const int r = row0 + q;              // warp-uniform
        if (r >= vocab) break;
        const float s  = hredsum(act ? dsel(v[q], v[q], half) : 0.f);
        const float d  = hredsum(act ? dsel(v[q], u4,  half) : 0.f);
        const float wd = hredsum(act ? dsel(v[q], w4,  half) : 0.f);
        if (lane == 0 || lane == 16) {
            const float a = __expf(d * rsqrtf(fmaxf(s, EPS2)) * uinv);
            // lane 0 -> (a0, a0*wd0) at .x; lane 16 -> (a1, a1*wd1) at .z
            float2* dst = (float2*)((float*)&g_vtab[r] + (lane >> 3));
            *dst = make_float2(a, a * wd);
        }
    }
}

// ---- Kernel 2: two warps per batch row (100 words each), smem combine. ----
__global__ __launch_bounds__(256)
void binclf_accum(const int* __restrict__ word_idxs,    // [B, 200]
                  float*     __restrict__ out,          // [B]
                  int B)
{
    __shared__ float4 spart[8];

    const int t    = threadIdx.x;
    const int lane = t & 31;
    const int w    = t >> 5;
    const int b    = blockIdx.x * 4 + (w >> 1);
    const int sub  = w & 1;

    float A0 = 0.f, P0 = 0.f, A1 = 0.f, P1 = 0.f;
    if (b < B) {
        const int* idxp = word_idxs + (size_t)b * SEQ_L + sub * 100;

        int idx[4];
        #pragma unroll
        for (int k = 0; k < 4; k++) {
            const int l = lane + 32 * k;
            idx[k] = (l < 100) ? __ldg(idxp + l) : -1;
        }

        #pragma unroll
        for (int k = 0; k < 4; k++) {
            if (idx[k] >= 0) {
                const float4 v = __ldg(&g_vtab[idx[k]]);
                A0 += v.x; P0 += v.y; A1 += v.z; P1 += v.w;
            }
        }

        A0 = wredsum(A0); P0 = wredsum(P0);
        A1 = wredsum(A1); P1 = wredsum(P1);
    }

    if (lane == 0) spart[w] = make_float4(A0, P0, A1, P1);
    __syncthreads();

    // One thread per b combines the two warp partials.
    if (t < 4) {
        const int bb = blockIdx.x * 4 + t;
        if (bb < B) {
            const float4 x = spart[2 * t];
            const float4 y = spart[2 * t + 1];
            out[bb] = (x.y + y.y) / (x.x + y.x) + (x.w + y.w) / (x.z + y.z);
        }
    }
}

extern "C" void kernel_launch(void* const* d_in, const int* in_sizes, int n_in,
                              void* d_out, int out_size)
{
    const int*   word_idxs = (const int*)  d_in[0];  // [B, 200] int32
    const float* emb_table = (const float*)d_in[1];  // [vocab, 100] f32
    const float* weights   = (const float*)d_in[2];  // [100, 1] f32
    const float* attend_u  = (const float*)d_in[3];  // [2, 50] f32
    float*       out       = (float*)d_out;          // [B] f32

    const int B     = in_sizes[0] / SEQ_L;
    const int vocab = in_sizes[1] / 100;

    binclf_vtab<<<(vocab + 31) / 32, 256>>>(emb_table, weights, attend_u, vocab);
    binclf_accum<<<(B + 3) / 4, 256>>>(word_idxs, out, B);
}

// round 12
// speedup vs baseline: 3.8023x; 1.3840x over previous
#include <cuda_runtime.h>
#include <stdint.h>
#include <math.h>

#define SEQ_L     200
#define EPS2      (1e-8f * 1e-8f)
#define VOCAB_MAX 100352

// Per-vocab precomputed table: (a0, a0*wd0, a1, a1*wd1)
__device__ float4 g_vtab[VOCAB_MAX];

__device__ __forceinline__ float wredsum(float x) {
    #pragma unroll
    for (int o = 16; o > 0; o >>= 1)
        x += __shfl_xor_sync(0xffffffffu, x, o);
    return x;
}

// ---- Kernel 1: per-vocab precompute, shuffle-free. ----
// Block stages 64 sequential rows (contiguous 25600-float copy), then one
// thread per (row, chunk) runs serial FMA chains over 13 float4s from smem.
#define VROWS 64
#define VNT   128

__global__ __launch_bounds__(VNT)
void binclf_vtab(const float* __restrict__ emb_table,   // [vocab, 100]
                 const float* __restrict__ weights,     // [100]
                 const float* __restrict__ attend_u,    // [100] chunk-major
                 int vocab)
{
    __shared__ float4 sv[VROWS * 25];   // 25600 B, stride 25 f4 (==1 mod 8: conflict-free)
    __shared__ float4 su[25];
    __shared__ float4 sw[25];

    const int t  = threadIdx.x;
    const int r0 = blockIdx.x * VROWS;

    if (t < 25)                 su[t]      = ((const float4*)attend_u)[t];
    else if (t >= 32 && t < 57) sw[t - 32] = ((const float4*)weights)[t - 32];

    // Linear coalesced copy of this block's row range (rows are sequential).
    const int nrows = min(VROWS, vocab - r0);
    const int nf4   = nrows * 25;
    const float4* src = (const float4*)(emb_table + (size_t)r0 * 100);
    #pragma unroll 4
    for (int j = t; j < nf4; j += VNT)
        sv[j] = __ldg(src + j);
    __syncthreads();

    // One thread per (row, chunk): warps 0-1 -> chunk 0, warps 2-3 -> chunk 1.
    const int c   = t >> 6;
    const int row = t & 63;
    if (row < nrows) {
        const float4* vp = sv + row * 25 + (c ? 13 : 0);
        const float4* up = su + (c ? 13 : 0);
        const float4* wp = sw + (c ? 13 : 0);

        float s = 0.f, d = 0.f, wd = 0.f, uu = 0.f;
        #pragma unroll
        for (int j = 0; j < 12; j++) {
            const float4 v = vp[j];
            const float4 u = up[j];     // warp-uniform broadcast
            const float4 q = wp[j];
            s  = fmaf(v.x, v.x, fmaf(v.y, v.y, fmaf(v.z, v.z, fmaf(v.w, v.w, s))));
            d  = fmaf(v.x, u.x, fmaf(v.y, u.y, fmaf(v.z, u.z, fmaf(v.w, u.w, d))));
            wd = fmaf(v.x, q.x, fmaf(v.y, q.y, fmaf(v.z, q.z, fmaf(v.w, q.w, wd))));
            uu = fmaf(u.x, u.x, fmaf(u.y, u.y, fmaf(u.z, u.z, fmaf(u.w, u.w, uu))));
        }
        // Boundary float4 #12 (floats 48-51): x,y -> chunk 0; z,w -> chunk 1.
        const float4 vb = sv[row * 25 + 12];
        const float4 ub = su[12];
        const float4 qb = sw[12];
        const float ex = c ? vb.z : vb.x,  ey = c ? vb.w : vb.y;
        const float ux = c ? ub.z : ub.x,  uy = c ? ub.w : ub.y;
        const float wx = c ? qb.z : qb.x,  wy = c ? qb.w : qb.y;
        s  = fmaf(ex, ex, fmaf(ey, ey, s));
        d  = fmaf(ex, ux, fmaf(ey, uy, d));
        wd = fmaf(ex, wx, fmaf(ey, wy, wd));
        uu = fmaf(ux, ux, fmaf(uy, uy, uu));

        const float a = __expf(d * rsqrtf(fmaxf(s, EPS2))
                                 * rsqrtf(fmaxf(uu, EPS2)));
        // chunk c owns the (2c, 2c+1) half of g_vtab[r]: disjoint 8-byte writes.
        float2* dst = (float2*)((float*)&g_vtab[r0 + row] + 2 * c);
        *dst = make_float2(a, a * wd);
    }
}

// ---- Kernel 2: two warps per batch row (100 words each), smem combine. ----
__global__ __launch_bounds__(256)
void binclf_accum(const int* __restrict__ word_idxs,    // [B, 200]
                  float*     __restrict__ out,          // [B]
                  int B)
{
    __shared__ float4 spart[8];

    const int t    = threadIdx.x;
    const int lane = t & 31;
    const int w    = t >> 5;
    const int b    = blockIdx.x * 4 + (w >> 1);
    const int sub  = w & 1;

    float A0 = 0.f, P0 = 0.f, A1 = 0.f, P1 = 0.f;
    if (b < B) {
        const int* idxp = word_idxs + (size_t)b * SEQ_L + sub * 100;

        int idx[4];
        #pragma unroll
        for (int k = 0; k < 4; k++) {
            const int l = lane + 32 * k;
            idx[k] = (l < 100) ? __ldg(idxp + l) : -1;
        }

        #pragma unroll
        for (int k = 0; k < 4; k++) {
            if (idx[k] >= 0) {
                const float4 v = __ldg(&g_vtab[idx[k]]);
                A0 += v.x; P0 += v.y; A1 += v.z; P1 += v.w;
            }
        }

        A0 = wredsum(A0); P0 = wredsum(P0);
        A1 = wredsum(A1); P1 = wredsum(P1);
    }

    if (lane == 0) spart[w] = make_float4(A0, P0, A1, P1);
    __syncthreads();

    if (t < 4) {
        const int bb = blockIdx.x * 4 + t;
        if (bb < B) {
            const float4 x = spart[2 * t];
            const float4 y = spart[2 * t + 1];
            out[bb] = (x.y + y.y) / (x.x + y.x) + (x.w + y.w) / (x.z + y.z);
        }
    }
}

extern "C" void kernel_launch(void* const* d_in, const int* in_sizes, int n_in,
                              void* d_out, int out_size)
{
    const int*   word_idxs = (const int*)  d_in[0];  // [B, 200] int32
    const float* emb_table = (const float*)d_in[1];  // [vocab, 100] f32
    const float* weights   = (const float*)d_in[2];  // [100, 1] f32
    const float* attend_u  = (const float*)d_in[3];  // [2, 50] f32
    float*       out       = (float*)d_out;          // [B] f32

    const int B     = in_sizes[0] / SEQ_L;
    const int vocab = in_sizes[1] / 100;

    binclf_vtab<<<(vocab + VROWS - 1) / VROWS, VNT>>>(emb_table, weights,
                                                      attend_u, vocab);
    binclf_accum<<<(B + 3) / 4, 256>>>(word_idxs, out, B);
}

// round 13
// speedup vs baseline: 4.3197x; 1.1361x over previous
#include <cuda_runtime.h>
#include <stdint.h>
#include <math.h>

#define SEQ_L     200
#define EPS2      (1e-8f * 1e-8f)
#define VOCAB_MAX 100352

// Per-vocab precomputed table: (a0, a0*wd0, a1, a1*wd1)
__device__ float4 g_vtab[VOCAB_MAX];

__device__ __forceinline__ float wredsum(float x) {
    #pragma unroll
    for (int o = 16; o > 0; o >>= 1)
        x += __shfl_xor_sync(0xffffffffu, x, o);
    return x;
}

__device__ __forceinline__ uint32_t smem_u32(const void* p) {
    return (uint32_t)__cvta_generic_to_shared(p);
}

// ---- Kernel 1: per-vocab precompute. TMA bulk-loads 96 sequential rows ----
// (one 38.4KB contiguous cp.async.bulk per block), then one thread per
// (row, chunk) runs serial FMA chains over 13 float4s from smem. No shuffles.
#define VROWS 96
#define VNT   192

__global__ __launch_bounds__(VNT)
void binclf_vtab(const float* __restrict__ emb_table,   // [vocab, 100]
                 const float* __restrict__ weights,     // [100]
                 const float* __restrict__ attend_u,    // [100] chunk-major
                 int vocab)
{
    __shared__ float4 sv[VROWS * 25];   // 38400 B, stride 25 f4 (1 mod 8: conflict-free)
    __shared__ float4 su[25];
    __shared__ float4 sw[25];
    __shared__ __align__(8) unsigned long long mbar;

    const int t  = threadIdx.x;
    const int r0 = blockIdx.x * VROWS;
    const int nrows = min(VROWS, vocab - r0);
    const unsigned int nbytes = (unsigned int)nrows * 400u;   // multiple of 16

    if (t < 25)                 su[t]      = ((const float4*)attend_u)[t];
    else if (t >= 32 && t < 57) sw[t - 32] = ((const float4*)weights)[t - 32];

    const uint32_t mb = smem_u32(&mbar);
    if (t == 0)
        asm volatile("mbarrier.init.shared.b64 [%0], %1;" :: "r"(mb), "r"(1) : "memory");
    __syncthreads();

    if (t == 0) {
        asm volatile("mbarrier.arrive.expect_tx.shared.b64 _, [%0], %1;"
                     :: "r"(mb), "r"(nbytes) : "memory");
        asm volatile("cp.async.bulk.shared::cta.global.mbarrier::complete_tx::bytes "
                     "[%0], [%1], %2, [%3];"
                     :: "r"(smem_u32(sv)),
                        "l"(emb_table + (size_t)r0 * 100),
                        "r"(nbytes), "r"(mb) : "memory");
    }

    // Wait for TMA completion (parity 0, single use per launch).
    {
        uint32_t done;
        asm volatile(
            "{\n\t.reg .pred p;\n\t"
            "mbarrier.try_wait.parity.shared.b64 p, [%1], 0;\n\t"
            "selp.b32 %0, 1, 0, p;\n\t}"
            : "=r"(done) : "r"(mb) : "memory");
        while (!done) {
            asm volatile(
                "{\n\t.reg .pred p;\n\t"
                "mbarrier.try_wait.parity.shared.b64 p, [%1], 0;\n\t"
                "selp.b32 %0, 1, 0, p;\n\t}"
                : "=r"(done) : "r"(mb) : "memory");
        }
    }
    __syncthreads();

    // One thread per (row, chunk): threads 0-95 chunk 0, 96-191 chunk 1.
    const int c   = t / VROWS;
    const int row = t - c * VROWS;
    if (row < nrows) {
        const float4* vp = sv + row * 25 + (c ? 13 : 0);
        const float4* up = su + (c ? 13 : 0);
        const float4* wp = sw + (c ? 13 : 0);

        float s = 0.f, d = 0.f, wd = 0.f, uu = 0.f;
        #pragma unroll
        for (int j = 0; j < 12; j++) {
            const float4 v = vp[j];
            const float4 u = up[j];     // warp-uniform broadcast
            const float4 q = wp[j];
            s  = fmaf(v.x, v.x, fmaf(v.y, v.y, fmaf(v.z, v.z, fmaf(v.w, v.w, s))));
            d  = fmaf(v.x, u.x, fmaf(v.y, u.y, fmaf(v.z, u.z, fmaf(v.w, u.w, d))));
            wd = fmaf(v.x, q.x, fmaf(v.y, q.y, fmaf(v.z, q.z, fmaf(v.w, q.w, wd))));
            uu = fmaf(u.x, u.x, fmaf(u.y, u.y, fmaf(u.z, u.z, fmaf(u.w, u.w, uu))));
        }
        // Boundary float4 #12 (floats 48-51): x,y -> chunk 0; z,w -> chunk 1.
        const float4 vb = sv[row * 25 + 12];
        const float4 ub = su[12];
        const float4 qb = sw[12];
        const float ex = c ? vb.z : vb.x,  ey = c ? vb.w : vb.y;
        const float ux = c ? ub.z : ub.x,  uy = c ? ub.w : ub.y;
        const float wx = c ? qb.z : qb.x,  wy = c ? qb.w : qb.y;
        s  = fmaf(ex, ex, fmaf(ey, ey, s));
        d  = fmaf(ex, ux, fmaf(ey, uy, d));
        wd = fmaf(ex, wx, fmaf(ey, wy, wd));
        uu = fmaf(ux, ux, fmaf(uy, uy, uu));

        const float a = __expf(d * rsqrtf(fmaxf(s, EPS2))
                                 * rsqrtf(fmaxf(uu, EPS2)));
        float2* dst = (float2*)((float*)&g_vtab[r0 + row] + 2 * c);
        *dst = make_float2(a, a * wd);
    }
}

// ---- Kernel 2: two warps per batch row (100 words each), smem combine. ----
__global__ __launch_bounds__(256)
void binclf_accum(const int* __restrict__ word_idxs,    // [B, 200]
                  float*     __restrict__ out,          // [B]
                  int B)
{
    __shared__ float4 spart[8];

    const int t    = threadIdx.x;
    const int lane = t & 31;
    const int w    = t >> 5;
    const int b    = blockIdx.x * 4 + (w >> 1);
    const int sub  = w & 1;

    float A0 = 0.f, P0 = 0.f, A1 = 0.f, P1 = 0.f;
    if (b < B) {
        const int* idxp = word_idxs + (size_t)b * SEQ_L + sub * 100;

        // Lanes 0..24 each own 4 consecutive words: one LDG.128 of indices.
        int4 idx = make_int4(-1, -1, -1, -1);
        if (lane < 25)
            idx = __ldg((const int4*)idxp + lane);

        if (idx.x >= 0) {
            const float4 v0 = __ldg(&g_vtab[idx.x]);
            const float4 v1 = __ldg(&g_vtab[idx.y]);
            const float4 v2 = __ldg(&g_vtab[idx.z]);
            const float4 v3 = __ldg(&g_vtab[idx.w]);
            A0 = v0.x + v1.x + v2.x + v3.x;
            P0 = v0.y + v1.y + v2.y + v3.y;
            A1 = v0.z + v1.z + v2.z + v3.z;
            P1 = v0.w + v1.w + v2.w + v3.w;
        }

        A0 = wredsum(A0); P0 = wredsum(P0);
        A1 = wredsum(A1); P1 = wredsum(P1);
    }

    if (lane == 0) spart[w] = make_float4(A0, P0, A1, P1);
    __syncthreads();

    if (t < 4) {
        const int bb = blockIdx.x * 4 + t;
        if (bb < B) {
            const float4 x = spart[2 * t];
            const float4 y = spart[2 * t + 1];
            out[bb] = (x.y + y.y) / (x.x + y.x) + (x.w + y.w) / (x.z + y.z);
        }
    }
}

extern "C" void kernel_launch(void* const* d_in, const int* in_sizes, int n_in,
                              void* d_out, int out_size)
{
    const int*   word_idxs = (const int*)  d_in[0];  // [B, 200] int32
    const float* emb_table = (const float*)d_in[1];  // [vocab, 100] f32
    const float* weights   = (const float*)d_in[2];  // [100, 1] f32
    const float* attend_u  = (const float*)d_in[3];  // [2, 50] f32
    float*       out       = (float*)d_out;          // [B] f32

    const int B     = in_sizes[0] / SEQ_L;
    const int vocab = in_sizes[1] / 100;

    binclf_vtab<<<(vocab + VROWS - 1) / VROWS, VNT>>>(emb_table, weights,
                                                      attend_u, vocab);
    binclf_accum<<<(B + 3) / 4, 256>>>(word_idxs, out, B);
}